// round 15
// baseline (speedup 1.0000x reference)
#include <cuda_runtime.h>
#include <cuda_bf16.h>
#include <math.h>
#include <stdint.h>

// ---------------- problem constants ----------------
#define Bq   4
#define Nn_  1024
#define DIM  512
#define Hh   8
#define DH   64
#define MLPD 2048
#define ROWS (Bq * Nn_)            // 4096 token rows
#define HB   (Hh * Bq)             // 32 attention batches
#define EPS  1e-5f
#define MST  80
#define KSPLIT 8

// ---------------- tf32 mma helpers ----------------
__device__ __forceinline__ float t32f(float x){
    unsigned r; asm("cvt.rna.tf32.f32 %0,%1;" : "=r"(r) : "f"(x));
    return __uint_as_float(r);
}
__device__ __forceinline__ void mma8(float* c, const unsigned* a, const unsigned* b){
    asm("mma.sync.aligned.m16n8k8.row.col.f32.tf32.tf32.f32 "
        "{%0,%1,%2,%3},{%4,%5,%6,%7},{%8,%9},{%0,%1,%2,%3};"
        : "+f"(c[0]), "+f"(c[1]), "+f"(c[2]), "+f"(c[3])
        : "r"(a[0]), "r"(a[1]), "r"(a[2]), "r"(a[3]), "r"(b[0]), "r"(b[1]));
}
__device__ __forceinline__ unsigned smem_u32(const void* p){
    return (unsigned)__cvta_generic_to_shared((void*)p);
}
__device__ __forceinline__ void cpa16(unsigned dst, const float* src){
    asm volatile("cp.async.cg.shared.global [%0], [%1], 16;" :: "r"(dst), "l"(src) : "memory");
}
__device__ __forceinline__ void cp_commit(){
    asm volatile("cp.async.commit_group;" ::: "memory");
}
__device__ __forceinline__ void cp_wait1(){
    asm volatile("cp.async.wait_group 1;" ::: "memory");
}

// ---------------- device scratch (no allocs allowed) ----------------
__device__ float g_xn [3 * ROWS * DIM];
__device__ float g_f  [3 * ROWS * DIM];
__device__ float g_ao [ROWS * DIM];
__device__ float g_q2 [ROWS * DIM];
__device__ float g_xn2[ROWS * DIM];
__device__ float g_u  [ROWS * MLPD];
__device__ float g_wr [2621440];                 // tf32-rounded weights
__device__ float g_Mr [HB][128][MST];            // Mcat (atomic-accumulated)
__device__ float g_qinv [HB * Nn_];
__device__ float g_qmean[HB * Nn_];
__device__ float g_qvar [HB * Nn_];
__device__ float g_kinv [HB * Nn_];
__device__ float g_kmean[HB * Nn_];
__device__ float g_kvar [HB * Nn_];
__device__ float g_hg [2 * Hh * DH];
__device__ float g_w3 [Hh * 3];

// rounded-weight offsets (floats)
#define WR_WIN  0
#define WR_WOUT 262144
#define WR_WUP  524288
#define WR_WDN  1572864

// ---------------- LN of q,k,v + zero g_hg/g_Mr + weight pre-round ----------
__global__ void ln3_kernel(const float* __restrict__ q, const float* __restrict__ k,
                           const float* __restrict__ v, const float* __restrict__ g,
                           const float* __restrict__ bb, float* __restrict__ y,
                           const float* __restrict__ Win, const float* __restrict__ Wout,
                           const float* __restrict__ Wup, const float* __restrict__ Wdn)
{
    const int tid = threadIdx.x, lane = tid & 31, wid = tid >> 5;
    if (blockIdx.x == 0) {
        *(float4*)&g_hg[tid * 4] = make_float4(0.f, 0.f, 0.f, 0.f);
    } else if (blockIdx.x <= 320) {
        float* mr = &g_Mr[0][0][0];
        *(float4*)&mr[(blockIdx.x - 1) * 1024 + tid * 4] = make_float4(0.f, 0.f, 0.f, 0.f);
    }
    {
        int i = blockIdx.x * 256 + tid;
#pragma unroll
        for (int rep = 0; rep < 2; rep++) {
            if (i < 655360) {
                const float* src; int dst;
                if (i < 65536)       { src = Win  + (size_t)i * 4;            dst = WR_WIN  + i * 4; }
                else if (i < 131072) { src = Wout + (size_t)(i - 65536) * 4;  dst = WR_WOUT + (i - 65536) * 4; }
                else if (i < 393216) { src = Wup  + (size_t)(i - 131072) * 4; dst = WR_WUP  + (i - 131072) * 4; }
                else                 { src = Wdn  + (size_t)(i - 393216) * 4; dst = WR_WDN  + (i - 393216) * 4; }
                float4 w = *(const float4*)src;
                *(float4*)&g_wr[dst] = make_float4(t32f(w.x), t32f(w.y), t32f(w.z), t32f(w.w));
            }
            i += 393216;
        }
    }
    const int row = blockIdx.x * 8 + wid;
    const int which = row >> 12;
    const float* x = (which == 0) ? q : (which == 1) ? k : v;
    const float* xr = x + (size_t)(row & (ROWS - 1)) * DIM;
    float4 a[4];
    float s = 0.f, ss = 0.f;
#pragma unroll
    for (int c = 0; c < 4; c++) {
        a[c] = *(const float4*)(xr + c * 128 + lane * 4);
        s  += a[c].x + a[c].y + a[c].z + a[c].w;
        ss += a[c].x * a[c].x + a[c].y * a[c].y + a[c].z * a[c].z + a[c].w * a[c].w;
    }
#pragma unroll
    for (int off = 16; off; off >>= 1) {
        s  += __shfl_xor_sync(0xffffffffu, s, off);
        ss += __shfl_xor_sync(0xffffffffu, ss, off);
    }
    const float mean = s * (1.f / DIM);
    const float var  = ss * (1.f / DIM) - mean * mean;
    const float inv  = rsqrtf(var + EPS);
    float* yr = y + (size_t)row * DIM;
#pragma unroll
    for (int c = 0; c < 4; c++) {
        float4 gv = *(const float4*)(g  + c * 128 + lane * 4);
        float4 bv = *(const float4*)(bb + c * 128 + lane * 4);
        float4 o;
        o.x = t32f((a[c].x - mean) * inv * gv.x + bv.x);
        o.y = t32f((a[c].y - mean) * inv * gv.y + bv.y);
        o.z = t32f((a[c].z - mean) * inv * gv.z + bv.z);
        o.w = t32f((a[c].w - mean) * inv * gv.w + bv.w);
        *(float4*)(yr + c * 128 + lane * 4) = o;
    }
}

// ---------------- warp-per-row LN (single tensor, LN2); tf32 output ----------
__global__ void ln_kernel(const float* __restrict__ x, const float* __restrict__ g,
                          const float* __restrict__ bb, float* __restrict__ y)
{
    const int tid = threadIdx.x, lane = tid & 31, wid = tid >> 5;
    const int row = blockIdx.x * 8 + wid;
    const float* xr = x + (size_t)row * DIM;
    float4 a[4];
    float s = 0.f, ss = 0.f;
#pragma unroll
    for (int c = 0; c < 4; c++) {
        a[c] = *(const float4*)(xr + c * 128 + lane * 4);
        s  += a[c].x + a[c].y + a[c].z + a[c].w;
        ss += a[c].x * a[c].x + a[c].y * a[c].y + a[c].z * a[c].z + a[c].w * a[c].w;
    }
#pragma unroll
    for (int off = 16; off; off >>= 1) {
        s  += __shfl_xor_sync(0xffffffffu, s, off);
        ss += __shfl_xor_sync(0xffffffffu, ss, off);
    }
    const float mean = s * (1.f / DIM);
    const float var  = ss * (1.f / DIM) - mean * mean;
    const float inv  = rsqrtf(var + EPS);
    float* yr = y + (size_t)row * DIM;
#pragma unroll
    for (int c = 0; c < 4; c++) {
        float4 gv = *(const float4*)(g  + c * 128 + lane * 4);
        float4 bv = *(const float4*)(bb + c * 128 + lane * 4);
        float4 o;
        o.x = t32f((a[c].x - mean) * inv * gv.x + bv.x);
        o.y = t32f((a[c].y - mean) * inv * gv.y + bv.y);
        o.z = t32f((a[c].z - mean) * inv * gv.z + bv.z);
        o.w = t32f((a[c].w - mean) * inv * gv.w + bv.w);
        *(float4*)(yr + c * 128 + lane * 4) = o;
    }
}

// ================ tf32 mma GEMM: BK=32, 3-stage cp.async pipeline ================
// C = A[M,K] @ W[N,K]^T.  CTA tile (MT*32) x 128. smem [TS][rows][36].
// MODE: 2 +bias+gelu(out rounded), 3 +bias+residual, 4 plain+round + fused stats
#define TS 3
#define SW 36

template <int MODE, int MT>
__global__ void __launch_bounds__(256) tmm3_kernel(
    const float* __restrict__ A, const float* __restrict__ W,
    const float* __restrict__ bias, const float* __restrict__ res,
    float* __restrict__ C, int M, int Nc, int K)
{
    constexpr int AR = MT * 32;
    extern __shared__ float sm[];
    float* Asm = sm;                        // [TS][AR][SW]
    float* Bsm = sm + TS * AR * SW;         // [TS][128][SW]
    __shared__ float sred[(MODE == 4) ? 8 * 4 * 8 * 4 : 4];
    __shared__ float colsum[(MODE == 4) ? 128 : 4];

    const int tid = threadIdx.x;
    const int lane = tid & 31, warp = tid >> 5;
    const int wm = (warp >> 2) * (MT * 16);
    const int wn = (warp & 3) * 32;
    const int m0 = blockIdx.y * AR, n0 = blockIdx.x * 128;
    const int g = lane >> 2, q4 = lane & 3;

    if (MODE == 4 && tid < 128) colsum[tid] = 0.f;

    float acc[MT][4][4];
#pragma unroll
    for (int i = 0; i < MT; i++)
#pragma unroll
        for (int j = 0; j < 4; j++)
#pragma unroll
            for (int c = 0; c < 4; c++) acc[i][j][c] = 0.f;

    const unsigned sAu = smem_u32(Asm);
    const unsigned sBu = smem_u32(Bsm);

    const int crow = tid >> 1, cko = (tid & 1) * 16;   // B and A(MT4): 2 thr/row, 4x16B
    const int arow2 = tid >> 2, ako2 = (tid & 3) * 8;  // A(MT2): 4 thr/row, 2x16B

    auto issue = [&](int s, int k0) {
        if (MT == 4) {
            unsigned d = sAu + (unsigned)(((s * 128 + crow) * SW + cko) * 4);
            const float* p = A + (size_t)(m0 + crow) * K + k0 + cko;
            cpa16(d, p); cpa16(d + 16, p + 4); cpa16(d + 32, p + 8); cpa16(d + 48, p + 12);
        } else {
            unsigned d = sAu + (unsigned)(((s * 64 + arow2) * SW + ako2) * 4);
            const float* p = A + (size_t)(m0 + arow2) * K + k0 + ako2;
            cpa16(d, p); cpa16(d + 16, p + 4);
        }
        unsigned d = sBu + (unsigned)(((s * 128 + crow) * SW + cko) * 4);
        const float* p = W + (size_t)(n0 + crow) * K + k0 + cko;
        cpa16(d, p); cpa16(d + 16, p + 4); cpa16(d + 32, p + 8); cpa16(d + 48, p + 12);
    };

    issue(0, 0);  cp_commit();
    issue(1, 32); cp_commit();

    const int L = K / 32;
    int s = 0;
    for (int j = 0; j < L; j++) {
        cp_wait1();
        __syncthreads();
#pragma unroll
        for (int kc = 0; kc < 32; kc += 8) {
            unsigned af[MT][4], bf[4][2];
#pragma unroll
            for (int mt = 0; mt < MT; mt++) {
                const float* ar = &Asm[(s * AR + wm + mt * 16 + g) * SW + kc + q4];
                af[mt][0] = __float_as_uint(ar[0]);
                af[mt][1] = __float_as_uint(ar[8 * SW]);
                af[mt][2] = __float_as_uint(ar[4]);
                af[mt][3] = __float_as_uint(ar[8 * SW + 4]);
            }
#pragma unroll
            for (int nt = 0; nt < 4; nt++) {
                const float* br = &Bsm[(s * 128 + wn + nt * 8 + g) * SW + kc + q4];
                bf[nt][0] = __float_as_uint(br[0]);
                bf[nt][1] = __float_as_uint(br[4]);
            }
#pragma unroll
            for (int mt = 0; mt < MT; mt++)
#pragma unroll
                for (int nt = 0; nt < 4; nt++)
                    mma8(acc[mt][nt], af[mt], bf[nt]);
        }
        if (j + 2 < L) {
            int ws = s + 2; if (ws >= TS) ws -= TS;
            issue(ws, (j + 2) * 32);
        }
        cp_commit();
        s++; if (s == TS) s = 0;
    }

    const int which = m0 >> 12;

    float csA[4], csB[4];
#pragma unroll
    for (int nt = 0; nt < 4; nt++) { csA[nt] = 0.f; csB[nt] = 0.f; }

#pragma unroll
    for (int mt = 0; mt < MT; mt++) {
        const int row0 = m0 + wm + mt * 16 + g;
        float s0 = 0.f, ss0 = 0.f, s1 = 0.f, ss1 = 0.f;
#pragma unroll
        for (int nt = 0; nt < 4; nt++) {
            const int col = n0 + wn + nt * 8 + 2 * q4;
            float v0 = acc[mt][nt][0], v1 = acc[mt][nt][1];
            float v2 = acc[mt][nt][2], v3 = acc[mt][nt][3];
            if (MODE == 2 || MODE == 3) {
                float2 bv = *(const float2*)&bias[col];
                v0 += bv.x; v1 += bv.y; v2 += bv.x; v3 += bv.y;
            }
            if (MODE == 2) {
                v0 = t32f(0.5f * v0 * (1.f + erff(v0 * 0.70710678118654752f)));
                v1 = t32f(0.5f * v1 * (1.f + erff(v1 * 0.70710678118654752f)));
                v2 = t32f(0.5f * v2 * (1.f + erff(v2 * 0.70710678118654752f)));
                v3 = t32f(0.5f * v3 * (1.f + erff(v3 * 0.70710678118654752f)));
            }
            if (MODE == 3) {
                float2 r0 = *(const float2*)(res + (size_t)row0 * Nc + col);
                float2 r1 = *(const float2*)(res + (size_t)(row0 + 8) * Nc + col);
                v0 += r0.x; v1 += r0.y; v2 += r1.x; v3 += r1.y;
            }
            if (MODE == 4) {
                v0 = t32f(v0); v1 = t32f(v1); v2 = t32f(v2); v3 = t32f(v3);
                s0 += v0 + v1; ss0 += v0 * v0 + v1 * v1;
                s1 += v2 + v3; ss1 += v2 * v2 + v3 * v3;
                csA[nt] += v0 + v2;
                csB[nt] += v1 + v3;
            }
            *(float2*)(C + (size_t)row0 * Nc + col)       = make_float2(v0, v1);
            *(float2*)(C + (size_t)(row0 + 8) * Nc + col) = make_float2(v2, v3);
        }
        if (MODE == 4) {
            s0 += __shfl_xor_sync(0xffffffffu, s0, 1);  s0 += __shfl_xor_sync(0xffffffffu, s0, 2);
            ss0 += __shfl_xor_sync(0xffffffffu, ss0, 1); ss0 += __shfl_xor_sync(0xffffffffu, ss0, 2);
            s1 += __shfl_xor_sync(0xffffffffu, s1, 1);  s1 += __shfl_xor_sync(0xffffffffu, s1, 2);
            ss1 += __shfl_xor_sync(0xffffffffu, ss1, 1); ss1 += __shfl_xor_sync(0xffffffffu, ss1, 2);
            if (q4 == 0) {
                float* sp = &sred[((warp * MT + mt) * 8 + g) * 4];
                sp[0] = s0; sp[1] = ss0; sp[2] = s1; sp[3] = ss1;
            }
        }
    }

    if (MODE == 4) {
        if (which < 2) {
#pragma unroll
            for (int nt = 0; nt < 4; nt++) {
                csA[nt] += __shfl_xor_sync(0xffffffffu, csA[nt], 4);
                csA[nt] += __shfl_xor_sync(0xffffffffu, csA[nt], 8);
                csA[nt] += __shfl_xor_sync(0xffffffffu, csA[nt], 16);
                csB[nt] += __shfl_xor_sync(0xffffffffu, csB[nt], 4);
                csB[nt] += __shfl_xor_sync(0xffffffffu, csB[nt], 8);
                csB[nt] += __shfl_xor_sync(0xffffffffu, csB[nt], 16);
                if (g == 0) {
                    atomicAdd(&colsum[wn + nt * 8 + 2 * q4],     csA[nt]);
                    atomicAdd(&colsum[wn + nt * 8 + 2 * q4 + 1], csB[nt]);
                }
            }
        }
        __syncthreads();
        if (which < 2) {
            if (tid < 128) atomicAdd(&g_hg[which * 512 + n0 + tid], colsum[tid]);
            const int p   = tid >> 6;
            const int mt2 = (tid >> 4) & 3;
            const int g2  = (tid >> 1) & 7;
            const int rr  = tid & 1;
            const int w0 = 2 * p;
            const float* e0 = &sred[((w0 * MT + mt2) * 8 + g2) * 4];
            const float* e1 = &sred[(((w0 + 1) * MT + mt2) * 8 + g2) * 4];
            float sA  = e0[2 * rr]     + e1[2 * rr];
            float ssA = e0[2 * rr + 1] + e1[2 * rr + 1];
            int row = m0 + (p >> 1) * 64 + mt2 * 16 + g2 + rr * 8;
            int lr2 = row & (ROWS - 1);
            int b3 = lr2 >> 10, n3 = lr2 & 1023;
            int head = (n0 >> 6) + (p & 1);
            int idx = (head * 4 + b3) * 1024 + n3;
            float mean = sA * (1.f / 64.f);
            float var  = (ssA - sA * sA * (1.f / 64.f)) * (1.f / 63.f);
            float inv  = rsqrtf(ssA);
            if (which == 0) { g_qinv[idx] = inv; g_qmean[idx] = mean; g_qvar[idx] = var; }
            else            { g_kinv[idx] = inv; g_kmean[idx] = mean; g_kvar[idx] = var; }
        }
    }
}

// ================ mbuild + folded gating MLP ================
__global__ void __launch_bounds__(256) mbuild_kernel(
    const float* __restrict__ W1, const float* __restrict__ b1,
    const float* __restrict__ gg, const float* __restrict__ gb,
    const float* __restrict__ W2, const float* __restrict__ b2)
{
    __shared__ float pool[9984];
    const int tid = threadIdx.x, lane = tid & 31, warp = tid >> 5;
    const int ks = blockIdx.x, hb = blockIdx.y;

    if (hb == HB) {
        if (ks != 0) return;
        float* W1s = pool;
        float* hgs = pool + 8192;
#pragma unroll
        for (int c = 0; c < 8; c++)
            *(float4*)&W1s[(c * 256 + tid) * 4] = *(const float4*)&W1[(c * 256 + tid) * 4];
        *(float4*)&hgs[tid * 4] = *(const float4*)&g_hg[tid * 4];
        __syncthreads();

        const int h = tid >> 5;
        const float invR = 1.f / (float)ROWS;
        float h1[2];
#pragma unroll
        for (int t = 0; t < 2; t++) {
            int j = lane + t * 32;
            const float* wrow = &W1s[j * 128];
            float dot = 0.f;
#pragma unroll 8
            for (int i = 0; i < 64; i++) dot += hgs[h * 64 + i] * wrow[i];
#pragma unroll 8
            for (int i = 0; i < 64; i++) dot += hgs[512 + h * 64 + i] * wrow[64 + i];
            h1[t] = b1[j] + dot * invR;
        }
        float s = h1[0] + h1[1], ss = h1[0] * h1[0] + h1[1] * h1[1];
#pragma unroll
        for (int off = 16; off; off >>= 1) {
            s  += __shfl_xor_sync(0xffffffffu, s, off);
            ss += __shfl_xor_sync(0xffffffffu, ss, off);
        }
        float mean = s * (1.f / 64.f);
        float var  = ss * (1.f / 64.f) - mean * mean;
        float inv  = rsqrtf(var + EPS);
        float hh[2];
#pragma unroll
        for (int t = 0; t < 2; t++) {
            int j = lane + t * 32;
            float vv = (h1[t] - mean) * inv * gg[j] + gb[j];
            hh[t] = fmaxf(vv, 0.f);
        }
        float lg[3];
#pragma unroll
        for (int c = 0; c < 3; c++) {
            float acc = hh[0] * W2[c * 64 + lane] + hh[1] * W2[c * 64 + lane + 32];
#pragma unroll
            for (int off = 16; off; off >>= 1) acc += __shfl_xor_sync(0xffffffffu, acc, off);
            lg[c] = acc + b2[c];
        }
        if (lane == 0) {
            float m = fmaxf(lg[0], fmaxf(lg[1], lg[2]));
            float e0 = expf(lg[0] - m), e1 = expf(lg[1] - m), e2 = expf(lg[2] - m);
            float inv_s = 1.f / (e0 + e1 + e2);
            g_w3[h * 3 + 0] = e0 * inv_s;
            g_w3[h * 3 + 1] = e1 * inv_s;
            g_w3[h * 3 + 2] = e2 * inv_s;
        }
        return;
    }

#define ASM(b, r) (&pool[((b) * 16 + (r)) * 136])
#define BSM(b, r) (&pool[6528 + ((b) * 16 + (r)) * 72])
    const int h = hb >> 2, b = hb & 3;
    const int base = hb * Nn_;
    const int g = lane >> 2, q4 = lane & 3;
    const int m0 = ks * (Nn_ / KSPLIT);

    const float* fk = g_f + (size_t)ROWS * DIM;
    const float* fv = g_f + 2 * (size_t)ROWS * DIM;

    float acc[9][4];
#pragma unroll
    for (int j = 0; j < 9; j++)
#pragma unroll
        for (int c = 0; c < 4; c++) acc[j][c] = 0.f;

    const int srow = tid >> 4;
    const int dc = (tid & 15) * 4;
    const int auxr = tid >> 3, auxs = tid & 7;

    auto store_chunk = [&](int sb, float4 vv, float4 kk, float ki, float xv) {
        float* ar = ASM(sb, srow) + 2 * dc;
        ar[0] = vv.x; ar[1] = t32f(ki*vv.x);
        ar[2] = vv.y; ar[3] = t32f(ki*vv.y);
        ar[4] = vv.z; ar[5] = t32f(ki*vv.z);
        ar[6] = vv.w; ar[7] = t32f(ki*vv.w);
        *(float4*)(BSM(sb, srow) + dc) = kk;
        if (tid < 128) BSM(sb, auxr)[64 + auxs] = xv;
    };
    auto load_chunk = [&](int k0, float4& vv, float4& kk, float& ki, float& xv) {
        int m = m0 + k0 + srow;
        vv = *(const float4*)(fv + (size_t)(b*Nn_ + m)*DIM + h*DH + dc);
        kk = *(const float4*)(fk + (size_t)(b*Nn_ + m)*DIM + h*DH + dc);
        ki = g_kinv[base + m];
        xv = 0.f;
        if (tid < 128) {
            int mm = m0 + k0 + auxr;
            if (auxs == 0) xv = t32f(g_kvar [base + mm]);
            else if (auxs == 1) xv = t32f(g_kmean[base + mm]);
        }
    };

    const int L = (Nn_ / KSPLIT) / 16;

    {
        float4 vv, kk; float ki, xv;
        load_chunk(0, vv, kk, ki, xv);
        store_chunk(0, vv, kk, ki, xv);
    }
    float4 vvC, kkC; float kiC = 0.f, xvC = 0.f;
    load_chunk(16, vvC, kkC, kiC, xvC);
    __syncthreads();

    for (int j = 0; j < L; j++) {
        float4 vvN, kkN; float kiN = 0.f, xvN = 0.f;
        if (j + 2 < L) load_chunk((j + 2) * 16, vvN, kkN, kiN, xvN);
        const int cb = j % 3;
#pragma unroll
        for (int ks8 = 0; ks8 < 16; ks8 += 8) {
            unsigned af[4];
            const int mr = warp * 16 + g;
            af[0] = __float_as_uint(ASM(cb, ks8 + q4)[mr]);
            af[1] = __float_as_uint(ASM(cb, ks8 + q4)[mr + 8]);
            af[2] = __float_as_uint(ASM(cb, ks8 + 4 + q4)[mr]);
            af[3] = __float_as_uint(ASM(cb, ks8 + 4 + q4)[mr + 8]);
#pragma unroll
            for (int nt = 0; nt < 9; nt++) {
                unsigned bf[2];
                bf[0] = __float_as_uint(BSM(cb, ks8 + q4)[nt * 8 + g]);
                bf[1] = __float_as_uint(BSM(cb, ks8 + 4 + q4)[nt * 8 + g]);
                mma8(acc[nt], af, bf);
            }
        }
        if (j + 1 < L) store_chunk((j + 1) % 3, vvC, kkC, kiC, xvC);
        __syncthreads();
        vvC = vvN; kkC = kkN; kiC = kiN; xvC = xvN;
    }

    const int row0 = warp * 16 + g;
#pragma unroll
    for (int nt = 0; nt < 9; nt++) {
        const int col = nt * 8 + 2 * q4;
        atomicAdd(&g_Mr[hb][row0][col],         acc[nt][0]);
        atomicAdd(&g_Mr[hb][row0][col + 1],     acc[nt][1]);
        atomicAdd(&g_Mr[hb][row0 + 8][col],     acc[nt][2]);
        atomicAdd(&g_Mr[hb][row0 + 8][col + 1], acc[nt][3]);
    }
#undef ASM
#undef BSM
}

// ================ pgemm: single smem fill (K=64), one barrier ================
__global__ void __launch_bounds__(256) pgemm_kernel()
{
    extern __shared__ float psm[];
    float* As = psm;                 // [64][136]
    float* Bs = psm + 64 * 136;      // [64][136]
    const int tid = threadIdx.x;
    const int lane = tid & 31, warp = tid >> 5;
    const int wm = (warp >> 2) * 64, wn = (warp & 3) * 32;
    const int hb = blockIdx.y, h = hb >> 2, b = hb & 3;
    const int q0 = blockIdx.x * 128;
    const int base = hb * Nn_;
    const int g = lane >> 2, q4 = lane & 3;

    const float* fq = g_f;

    float acc[4][4][4];
#pragma unroll
    for (int i = 0; i < 4; i++)
#pragma unroll
        for (int j = 0; j < 4; j++)
#pragma unroll
            for (int c = 0; c < 4; c++) acc[i][j][c] = 0.f;

    const int srow = tid >> 1, skc = (tid & 1) * 8;
    const float* Apt = fq + (size_t)(b * Nn_ + q0 + srow) * DIM + h * DH + skc;
    const float* Wpt = &g_Mr[hb][srow][skc];

#pragma unroll
    for (int k0 = 0; k0 < DH; k0 += 16) {
        float4 a0 = *(const float4*)(Apt + k0);
        float4 a1 = *(const float4*)(Apt + k0 + 4);
        float4 w0 = *(const float4*)(Wpt + k0);
        float4 w1 = *(const float4*)(Wpt + k0 + 4);
        float* ac = &As[(k0 + skc) * 136 + srow];
        ac[0*136] = a0.x; ac[1*136] = a0.y; ac[2*136] = a0.z; ac[3*136] = a0.w;
        ac[4*136] = a1.x; ac[5*136] = a1.y; ac[6*136] = a1.z; ac[7*136] = a1.w;
        float* bc = &Bs[(k0 + skc) * 136 + srow];
        bc[0*136] = t32f(w0.x); bc[1*136] = t32f(w0.y); bc[2*136] = t32f(w0.z); bc[3*136] = t32f(w0.w);
        bc[4*136] = t32f(w1.x); bc[5*136] = t32f(w1.y); bc[6*136] = t32f(w1.z); bc[7*136] = t32f(w1.w);
    }
    __syncthreads();

#pragma unroll
    for (int ks = 0; ks < DH; ks += 8) {
        unsigned af[4][4], bf[4][2];
#pragma unroll
        for (int mt = 0; mt < 4; mt++) {
            int mr = wm + mt * 16 + g;
            af[mt][0] = __float_as_uint(As[(ks + q4) * 136 + mr]);
            af[mt][1] = __float_as_uint(As[(ks + q4) * 136 + mr + 8]);
            af[mt][2] = __float_as_uint(As[(ks + 4 + q4) * 136 + mr]);
            af[mt][3] = __float_as_uint(As[(ks + 4 + q4) * 136 + mr + 8]);
        }
#pragma unroll
        for (int nt = 0; nt < 4; nt++) {
            int nc = wn + nt * 8 + g;
            bf[nt][0] = __float_as_uint(Bs[(ks + q4) * 136 + nc]);
            bf[nt][1] = __float_as_uint(Bs[(ks + 4 + q4) * 136 + nc]);
        }
#pragma unroll
        for (int mt = 0; mt < 4; mt++)
#pragma unroll
            for (int nt = 0; nt < 4; nt++)
                mma8(acc[mt][nt], af[mt], bf[nt]);
    }

    const float cw = g_w3[h * 3 + 0], covw = g_w3[h * 3 + 1], vw = g_w3[h * 3 + 2];
#pragma unroll
    for (int mt = 0; mt < 4; mt++) {
        const int row0 = q0 + wm + mt * 16 + g;
        const float qi0 = g_qinv[base + row0],     qm0 = g_qmean[base + row0],     qv0 = g_qvar[base + row0];
        const float qi1 = g_qinv[base + row0 + 8], qm1 = g_qmean[base + row0 + 8], qv1 = g_qvar[base + row0 + 8];
#pragma unroll
        for (int nt = 0; nt < 4; nt++) {
            const int col = wn + nt * 8 + 2 * q4;
            const int d = col >> 1;
            const float Skv = g_Mr[hb][col][64];
            const float Skm = g_Mr[hb][col][65];
            float o0 = cw * qi0 * acc[mt][nt][1] + (covw / DH) * acc[mt][nt][0]
                     + (vw / DH) * qv0 * Skv - covw * qm0 * Skm;
            float o1 = cw * qi1 * acc[mt][nt][3] + (covw / DH) * acc[mt][nt][2]
                     + (vw / DH) * qv1 * Skv - covw * qm1 * Skm;
            g_ao[(size_t)(b * Nn_ + row0) * DIM + h * DH + d]     = t32f(o0);
            g_ao[(size_t)(b * Nn_ + row0 + 8) * DIM + h * DH + d] = t32f(o1);
        }
    }
}

// ---------------- launch ----------------
extern "C" void kernel_launch(void* const* d_in, const int* in_sizes, int n_in,
                              void* d_out, int out_size)
{
    const float* q    = (const float*)d_in[0];
    const float* k    = (const float*)d_in[1];
    const float* v    = (const float*)d_in[2];
    const float* Win  = (const float*)d_in[3];
    const float* Wout = (const float*)d_in[4];
    const float* bout = (const float*)d_in[5];
    const float* g1   = (const float*)d_in[6];
    const float* b1n  = (const float*)d_in[7];
    const float* g2   = (const float*)d_in[8];
    const float* b2n  = (const float*)d_in[9];
    const float* Wup  = (const float*)d_in[10];
    const float* bup  = (const float*)d_in[11];
    const float* Wdn  = (const float*)d_in[12];
    const float* bdn  = (const float*)d_in[13];
    const float* wpW1 = (const float*)d_in[14];
    const float* wpb1 = (const float*)d_in[15];
    const float* wpg  = (const float*)d_in[16];
    const float* wpb  = (const float*)d_in[17];
    const float* wpW2 = (const float*)d_in[18];
    const float* wpb2 = (const float*)d_in[19];
    float* out = (float*)d_out;

    float* xn;  cudaGetSymbolAddress((void**)&xn,  g_xn);
    float* f;   cudaGetSymbolAddress((void**)&f,   g_f);
    float* ao;  cudaGetSymbolAddress((void**)&ao,  g_ao);
    float* q2;  cudaGetSymbolAddress((void**)&q2,  g_q2);
    float* xn2; cudaGetSymbolAddress((void**)&xn2, g_xn2);
    float* u;   cudaGetSymbolAddress((void**)&u,   g_u);
    float* wr;  cudaGetSymbolAddress((void**)&wr,  g_wr);

    const int smem4 = TS * (128 + 128) * SW * 4;   // 110592 B (MT=4)
    const int smem2 = TS * (64 + 128) * SW * 4;    // 82944 B (MT=2)
    const int psmem = 2 * 64 * 136 * 4;            // 69632 B (pgemm)
    cudaFuncSetAttribute(tmm3_kernel<4,4>, cudaFuncAttributeMaxDynamicSharedMemorySize, smem4);
    cudaFuncSetAttribute(tmm3_kernel<2,4>, cudaFuncAttributeMaxDynamicSharedMemorySize, smem4);
    cudaFuncSetAttribute(tmm3_kernel<3,2>, cudaFuncAttributeMaxDynamicSharedMemorySize, smem2);
    cudaFuncSetAttribute(pgemm_kernel,     cudaFuncAttributeMaxDynamicSharedMemorySize, psmem);

    // 1. fused LN of q,k,v (tf32 out; also zeroes g_hg/g_Mr + rounds weights)
    ln3_kernel<<<3 * ROWS / 8, 256>>>(q, k, v, g1, b1n, xn, Win, Wout, Wup, Wdn);

    // 2. fused projection + per-row stats + per-head column sums
    tmm3_kernel<4, 4><<<dim3(DIM / 128, 3 * ROWS / 128), 256, smem4>>>(
        xn, wr + WR_WIN, nullptr, nullptr, f, 3 * ROWS, DIM, DIM);

    // 3. attention: Mcat build (+ folded gating MLP block) -> pgemm
    mbuild_kernel<<<dim3(KSPLIT, HB + 1), 256>>>(wpW1, wpb1, wpg, wpb, wpW2, wpb2);
    pgemm_kernel<<<dim3(Nn_ / 128, HB), 256, psmem>>>();

    // 4. attn out proj + residual -> q2
    tmm3_kernel<3, 2><<<dim3(DIM / 128, ROWS / 64), 256, smem2>>>(
        ao, wr + WR_WOUT, bout, q, q2, ROWS, DIM, DIM);

    // 5. LN2 (tf32 out)
    ln_kernel<<<ROWS / 8, 256>>>(q2, g2, b2n, xn2);

    // 6. MLP up + gelu (tf32 out)
    tmm3_kernel<2, 4><<<dim3(MLPD / 128, ROWS / 128), 256, smem4>>>(
        xn2, wr + WR_WUP, bup, nullptr, u, ROWS, MLPD, DIM);

    // 7. MLP down + residual -> out
    tmm3_kernel<3, 2><<<dim3(DIM / 128, ROWS / 64), 256, smem2>>>(
        u, wr + WR_WDN, bdn, q2, out, ROWS, DIM, MLPD);
}

// round 16
// speedup vs baseline: 1.0560x; 1.0560x over previous
#include <cuda_runtime.h>
#include <cuda_bf16.h>
#include <math.h>
#include <stdint.h>

// ---------------- problem constants ----------------
#define Bq   4
#define Nn_  1024
#define DIM  512
#define Hh   8
#define DH   64
#define MLPD 2048
#define ROWS (Bq * Nn_)            // 4096 token rows
#define HB   (Hh * Bq)             // 32 attention batches
#define EPS  1e-5f
#define MST  80
#define KSPLIT 8

// ---------------- tf32 mma helpers ----------------
__device__ __forceinline__ float t32f(float x){
    unsigned r; asm("cvt.rna.tf32.f32 %0,%1;" : "=r"(r) : "f"(x));
    return __uint_as_float(r);
}
__device__ __forceinline__ void mma8(float* c, const unsigned* a, const unsigned* b){
    asm("mma.sync.aligned.m16n8k8.row.col.f32.tf32.tf32.f32 "
        "{%0,%1,%2,%3},{%4,%5,%6,%7},{%8,%9},{%0,%1,%2,%3};"
        : "+f"(c[0]), "+f"(c[1]), "+f"(c[2]), "+f"(c[3])
        : "r"(a[0]), "r"(a[1]), "r"(a[2]), "r"(a[3]), "r"(b[0]), "r"(b[1]));
}
__device__ __forceinline__ unsigned smem_u32(const void* p){
    return (unsigned)__cvta_generic_to_shared((void*)p);
}
__device__ __forceinline__ void cpa16(unsigned dst, const float* src){
    asm volatile("cp.async.cg.shared.global [%0], [%1], 16;" :: "r"(dst), "l"(src) : "memory");
}
__device__ __forceinline__ void cp_commit(){
    asm volatile("cp.async.commit_group;" ::: "memory");
}
__device__ __forceinline__ void cp_wait3(){
    asm volatile("cp.async.wait_group 3;" ::: "memory");
}

// ---------------- device scratch (no allocs allowed) ----------------
__device__ float g_xn [3 * ROWS * DIM];
__device__ float g_f  [3 * ROWS * DIM];
__device__ float g_ao [ROWS * DIM];
__device__ float g_q2 [ROWS * DIM];
__device__ float g_xn2[ROWS * DIM];
__device__ float g_u  [ROWS * MLPD];
__device__ float g_wr [2621440];                 // tf32-rounded weights
__device__ float g_Mr [HB][128][MST];            // Mcat (atomic-accumulated)
__device__ float g_qinv [HB * Nn_];
__device__ float g_qmean[HB * Nn_];
__device__ float g_qvar [HB * Nn_];
__device__ float g_kinv [HB * Nn_];
__device__ float g_kmean[HB * Nn_];
__device__ float g_kvar [HB * Nn_];
__device__ float g_hg [2 * Hh * DH];
__device__ float g_w3 [Hh * 3];

// rounded-weight offsets (floats)
#define WR_WIN  0
#define WR_WOUT 262144
#define WR_WUP  524288
#define WR_WDN  1572864

// ---------------- LN of q,k,v + zero g_hg/g_Mr + weight pre-round ----------
__global__ void ln3_kernel(const float* __restrict__ q, const float* __restrict__ k,
                           const float* __restrict__ v, const float* __restrict__ g,
                           const float* __restrict__ bb, float* __restrict__ y,
                           const float* __restrict__ Win, const float* __restrict__ Wout,
                           const float* __restrict__ Wup, const float* __restrict__ Wdn)
{
    const int tid = threadIdx.x, lane = tid & 31, wid = tid >> 5;
    if (blockIdx.x == 0) {
        *(float4*)&g_hg[tid * 4] = make_float4(0.f, 0.f, 0.f, 0.f);
    } else if (blockIdx.x <= 320) {
        float* mr = &g_Mr[0][0][0];
        *(float4*)&mr[(blockIdx.x - 1) * 1024 + tid * 4] = make_float4(0.f, 0.f, 0.f, 0.f);
    }
    {
        int i = blockIdx.x * 256 + tid;
#pragma unroll
        for (int rep = 0; rep < 2; rep++) {
            if (i < 655360) {
                const float* src; int dst;
                if (i < 65536)       { src = Win  + (size_t)i * 4;            dst = WR_WIN  + i * 4; }
                else if (i < 131072) { src = Wout + (size_t)(i - 65536) * 4;  dst = WR_WOUT + (i - 65536) * 4; }
                else if (i < 393216) { src = Wup  + (size_t)(i - 131072) * 4; dst = WR_WUP  + (i - 131072) * 4; }
                else                 { src = Wdn  + (size_t)(i - 393216) * 4; dst = WR_WDN  + (i - 393216) * 4; }
                float4 w = *(const float4*)src;
                *(float4*)&g_wr[dst] = make_float4(t32f(w.x), t32f(w.y), t32f(w.z), t32f(w.w));
            }
            i += 393216;
        }
    }
    const int row = blockIdx.x * 8 + wid;
    const int which = row >> 12;
    const float* x = (which == 0) ? q : (which == 1) ? k : v;
    const float* xr = x + (size_t)(row & (ROWS - 1)) * DIM;
    float4 a[4];
    float s = 0.f, ss = 0.f;
#pragma unroll
    for (int c = 0; c < 4; c++) {
        a[c] = *(const float4*)(xr + c * 128 + lane * 4);
        s  += a[c].x + a[c].y + a[c].z + a[c].w;
        ss += a[c].x * a[c].x + a[c].y * a[c].y + a[c].z * a[c].z + a[c].w * a[c].w;
    }
#pragma unroll
    for (int off = 16; off; off >>= 1) {
        s  += __shfl_xor_sync(0xffffffffu, s, off);
        ss += __shfl_xor_sync(0xffffffffu, ss, off);
    }
    const float mean = s * (1.f / DIM);
    const float var  = ss * (1.f / DIM) - mean * mean;
    const float inv  = rsqrtf(var + EPS);
    float* yr = y + (size_t)row * DIM;
#pragma unroll
    for (int c = 0; c < 4; c++) {
        float4 gv = *(const float4*)(g  + c * 128 + lane * 4);
        float4 bv = *(const float4*)(bb + c * 128 + lane * 4);
        float4 o;
        o.x = t32f((a[c].x - mean) * inv * gv.x + bv.x);
        o.y = t32f((a[c].y - mean) * inv * gv.y + bv.y);
        o.z = t32f((a[c].z - mean) * inv * gv.z + bv.z);
        o.w = t32f((a[c].w - mean) * inv * gv.w + bv.w);
        *(float4*)(yr + c * 128 + lane * 4) = o;
    }
}

// ---------------- warp-per-row LN (single tensor, LN2); tf32 output ----------
__global__ void ln_kernel(const float* __restrict__ x, const float* __restrict__ g,
                          const float* __restrict__ bb, float* __restrict__ y)
{
    const int tid = threadIdx.x, lane = tid & 31, wid = tid >> 5;
    const int row = blockIdx.x * 8 + wid;
    const float* xr = x + (size_t)row * DIM;
    float4 a[4];
    float s = 0.f, ss = 0.f;
#pragma unroll
    for (int c = 0; c < 4; c++) {
        a[c] = *(const float4*)(xr + c * 128 + lane * 4);
        s  += a[c].x + a[c].y + a[c].z + a[c].w;
        ss += a[c].x * a[c].x + a[c].y * a[c].y + a[c].z * a[c].z + a[c].w * a[c].w;
    }
#pragma unroll
    for (int off = 16; off; off >>= 1) {
        s  += __shfl_xor_sync(0xffffffffu, s, off);
        ss += __shfl_xor_sync(0xffffffffu, ss, off);
    }
    const float mean = s * (1.f / DIM);
    const float var  = ss * (1.f / DIM) - mean * mean;
    const float inv  = rsqrtf(var + EPS);
    float* yr = y + (size_t)row * DIM;
#pragma unroll
    for (int c = 0; c < 4; c++) {
        float4 gv = *(const float4*)(g  + c * 128 + lane * 4);
        float4 bv = *(const float4*)(bb + c * 128 + lane * 4);
        float4 o;
        o.x = t32f((a[c].x - mean) * inv * gv.x + bv.x);
        o.y = t32f((a[c].y - mean) * inv * gv.y + bv.y);
        o.z = t32f((a[c].z - mean) * inv * gv.z + bv.z);
        o.w = t32f((a[c].w - mean) * inv * gv.w + bv.w);
        *(float4*)(yr + c * 128 + lane * 4) = o;
    }
}

// ================ tf32 mma GEMM, 5-stage cp.async pipeline (BK=16) ===========
#define TS 5

template <int MODE, int MT>
__global__ void __launch_bounds__(256) tmm3_kernel(
    const float* __restrict__ A, const float* __restrict__ W,
    const float* __restrict__ bias, const float* __restrict__ res,
    float* __restrict__ C, int M, int Nc, int K)
{
    constexpr int AR = MT * 32;
    extern __shared__ float sm[];
    float* Asm = sm;                        // [TS][AR][20]
    float* Bsm = sm + TS * AR * 20;         // [TS][128][20]
    __shared__ float sred[(MODE == 4) ? 8 * 4 * 8 * 4 : 4];
    __shared__ float colsum[(MODE == 4) ? 128 : 4];

    const int tid = threadIdx.x;
    const int lane = tid & 31, warp = tid >> 5;
    const int wm = (warp >> 2) * (MT * 16);
    const int wn = (warp & 3) * 32;
    const int m0 = blockIdx.y * AR, n0 = blockIdx.x * 128;
    const int g = lane >> 2, q4 = lane & 3;

    if (MODE == 4 && tid < 128) colsum[tid] = 0.f;

    float acc[MT][4][4];
#pragma unroll
    for (int i = 0; i < MT; i++)
#pragma unroll
        for (int j = 0; j < 4; j++)
#pragma unroll
            for (int c = 0; c < 4; c++) acc[i][j][c] = 0.f;

    const unsigned sAu = smem_u32(Asm);
    const unsigned sBu = smem_u32(Bsm);

    const int crow = tid >> 1, cko = (tid & 1) * 8;
    const int arow2 = tid >> 2, ako2 = (tid & 3) * 4;

    auto issue = [&](int s, int k0) {
        if (MT == 4) {
            unsigned d = sAu + (unsigned)(((s * 128 + crow) * 20 + cko) * 4);
            const float* p = A + (size_t)(m0 + crow) * K + k0 + cko;
            cpa16(d, p); cpa16(d + 16, p + 4);
        } else {
            unsigned d = sAu + (unsigned)(((s * 64 + arow2) * 20 + ako2) * 4);
            cpa16(d, A + (size_t)(m0 + arow2) * K + k0 + ako2);
        }
        unsigned d = sBu + (unsigned)(((s * 128 + crow) * 20 + cko) * 4);
        const float* p = W + (size_t)(n0 + crow) * K + k0 + cko;
        cpa16(d, p); cpa16(d + 16, p + 4);
    };

    issue(0, 0);  cp_commit();
    issue(1, 16); cp_commit();
    issue(2, 32); cp_commit();
    issue(3, 48); cp_commit();

    const int L = K / 16;
    int s = 0;
    for (int j = 0; j < L; j++) {
        cp_wait3();
        __syncthreads();
#pragma unroll
        for (int kc = 0; kc < 16; kc += 8) {
            unsigned af[MT][4], bf[4][2];
#pragma unroll
            for (int mt = 0; mt < MT; mt++) {
                const float* ar = &Asm[(s * AR + wm + mt * 16 + g) * 20 + kc + q4];
                af[mt][0] = __float_as_uint(ar[0]);
                af[mt][1] = __float_as_uint(ar[160]);
                af[mt][2] = __float_as_uint(ar[4]);
                af[mt][3] = __float_as_uint(ar[164]);
            }
#pragma unroll
            for (int nt = 0; nt < 4; nt++) {
                const float* br = &Bsm[(s * 128 + wn + nt * 8 + g) * 20 + kc + q4];
                bf[nt][0] = __float_as_uint(br[0]);
                bf[nt][1] = __float_as_uint(br[4]);
            }
#pragma unroll
            for (int mt = 0; mt < MT; mt++)
#pragma unroll
                for (int nt = 0; nt < 4; nt++)
                    mma8(acc[mt][nt], af[mt], bf[nt]);
        }
        if (j + 4 < L) {
            int ws = s + 4; if (ws >= TS) ws -= TS;
            issue(ws, (j + 4) * 16);
        }
        cp_commit();
        s++; if (s == TS) s = 0;
    }

    const int which = m0 >> 12;

    float csA[4], csB[4];
#pragma unroll
    for (int nt = 0; nt < 4; nt++) { csA[nt] = 0.f; csB[nt] = 0.f; }

#pragma unroll
    for (int mt = 0; mt < MT; mt++) {
        const int row0 = m0 + wm + mt * 16 + g;
        float s0 = 0.f, ss0 = 0.f, s1 = 0.f, ss1 = 0.f;
#pragma unroll
        for (int nt = 0; nt < 4; nt++) {
            const int col = n0 + wn + nt * 8 + 2 * q4;
            float v0 = acc[mt][nt][0], v1 = acc[mt][nt][1];
            float v2 = acc[mt][nt][2], v3 = acc[mt][nt][3];
            if (MODE == 2 || MODE == 3) {
                float2 bv = *(const float2*)&bias[col];
                v0 += bv.x; v1 += bv.y; v2 += bv.x; v3 += bv.y;
            }
            if (MODE == 2) {
                v0 = t32f(0.5f * v0 * (1.f + erff(v0 * 0.70710678118654752f)));
                v1 = t32f(0.5f * v1 * (1.f + erff(v1 * 0.70710678118654752f)));
                v2 = t32f(0.5f * v2 * (1.f + erff(v2 * 0.70710678118654752f)));
                v3 = t32f(0.5f * v3 * (1.f + erff(v3 * 0.70710678118654752f)));
            }
            if (MODE == 3) {
                float2 r0 = *(const float2*)(res + (size_t)row0 * Nc + col);
                float2 r1 = *(const float2*)(res + (size_t)(row0 + 8) * Nc + col);
                v0 += r0.x; v1 += r0.y; v2 += r1.x; v3 += r1.y;
            }
            if (MODE == 4) {
                v0 = t32f(v0); v1 = t32f(v1); v2 = t32f(v2); v3 = t32f(v3);
                s0 += v0 + v1; ss0 += v0 * v0 + v1 * v1;
                s1 += v2 + v3; ss1 += v2 * v2 + v3 * v3;
                csA[nt] += v0 + v2;
                csB[nt] += v1 + v3;
            }
            *(float2*)(C + (size_t)row0 * Nc + col)       = make_float2(v0, v1);
            *(float2*)(C + (size_t)(row0 + 8) * Nc + col) = make_float2(v2, v3);
        }
        if (MODE == 4) {
            s0 += __shfl_xor_sync(0xffffffffu, s0, 1);  s0 += __shfl_xor_sync(0xffffffffu, s0, 2);
            ss0 += __shfl_xor_sync(0xffffffffu, ss0, 1); ss0 += __shfl_xor_sync(0xffffffffu, ss0, 2);
            s1 += __shfl_xor_sync(0xffffffffu, s1, 1);  s1 += __shfl_xor_sync(0xffffffffu, s1, 2);
            ss1 += __shfl_xor_sync(0xffffffffu, ss1, 1); ss1 += __shfl_xor_sync(0xffffffffu, ss1, 2);
            if (q4 == 0) {
                float* sp = &sred[((warp * MT + mt) * 8 + g) * 4];
                sp[0] = s0; sp[1] = ss0; sp[2] = s1; sp[3] = ss1;
            }
        }
    }

    if (MODE == 4) {
        if (which < 2) {
#pragma unroll
            for (int nt = 0; nt < 4; nt++) {
                csA[nt] += __shfl_xor_sync(0xffffffffu, csA[nt], 4);
                csA[nt] += __shfl_xor_sync(0xffffffffu, csA[nt], 8);
                csA[nt] += __shfl_xor_sync(0xffffffffu, csA[nt], 16);
                csB[nt] += __shfl_xor_sync(0xffffffffu, csB[nt], 4);
                csB[nt] += __shfl_xor_sync(0xffffffffu, csB[nt], 8);
                csB[nt] += __shfl_xor_sync(0xffffffffu, csB[nt], 16);
                if (g == 0) {
                    atomicAdd(&colsum[wn + nt * 8 + 2 * q4],     csA[nt]);
                    atomicAdd(&colsum[wn + nt * 8 + 2 * q4 + 1], csB[nt]);
                }
            }
        }
        __syncthreads();
        if (which < 2) {
            if (tid < 128) atomicAdd(&g_hg[which * 512 + n0 + tid], colsum[tid]);
            const int p   = tid >> 6;
            const int mt2 = (tid >> 4) & 3;
            const int g2  = (tid >> 1) & 7;
            const int rr  = tid & 1;
            const int w0 = 2 * p;
            const float* e0 = &sred[((w0 * MT + mt2) * 8 + g2) * 4];
            const float* e1 = &sred[(((w0 + 1) * MT + mt2) * 8 + g2) * 4];
            float sA  = e0[2 * rr]     + e1[2 * rr];
            float ssA = e0[2 * rr + 1] + e1[2 * rr + 1];
            int row = m0 + (p >> 1) * 64 + mt2 * 16 + g2 + rr * 8;
            int lr2 = row & (ROWS - 1);
            int b3 = lr2 >> 10, n3 = lr2 & 1023;
            int head = (n0 >> 6) + (p & 1);
            int idx = (head * 4 + b3) * 1024 + n3;
            float mean = sA * (1.f / 64.f);
            float var  = (ssA - sA * sA * (1.f / 64.f)) * (1.f / 63.f);
            float inv  = rsqrtf(ssA);
            if (which == 0) { g_qinv[idx] = inv; g_qmean[idx] = mean; g_qvar[idx] = var; }
            else            { g_kinv[idx] = inv; g_kmean[idx] = mean; g_kvar[idx] = var; }
        }
    }
}

// ================ mbuild + folded gating MLP ================
__global__ void __launch_bounds__(256) mbuild_kernel(
    const float* __restrict__ W1, const float* __restrict__ b1,
    const float* __restrict__ gg, const float* __restrict__ gb,
    const float* __restrict__ W2, const float* __restrict__ b2)
{
    __shared__ float pool[9984];
    const int tid = threadIdx.x, lane = tid & 31, warp = tid >> 5;
    const int ks = blockIdx.x, hb = blockIdx.y;

    if (hb == HB) {
        if (ks != 0) return;
        float* W1s = pool;
        float* hgs = pool + 8192;
#pragma unroll
        for (int c = 0; c < 8; c++)
            *(float4*)&W1s[(c * 256 + tid) * 4] = *(const float4*)&W1[(c * 256 + tid) * 4];
        *(float4*)&hgs[tid * 4] = *(const float4*)&g_hg[tid * 4];
        __syncthreads();

        const int h = tid >> 5;
        const float invR = 1.f / (float)ROWS;
        float h1[2];
#pragma unroll
        for (int t = 0; t < 2; t++) {
            int j = lane + t * 32;
            const float* wrow = &W1s[j * 128];
            float dot = 0.f;
#pragma unroll 8
            for (int i = 0; i < 64; i++) dot += hgs[h * 64 + i] * wrow[i];
#pragma unroll 8
            for (int i = 0; i < 64; i++) dot += hgs[512 + h * 64 + i] * wrow[64 + i];
            h1[t] = b1[j] + dot * invR;
        }
        float s = h1[0] + h1[1], ss = h1[0] * h1[0] + h1[1] * h1[1];
#pragma unroll
        for (int off = 16; off; off >>= 1) {
            s  += __shfl_xor_sync(0xffffffffu, s, off);
            ss += __shfl_xor_sync(0xffffffffu, ss, off);
        }
        float mean = s * (1.f / 64.f);
        float var  = ss * (1.f / 64.f) - mean * mean;
        float inv  = rsqrtf(var + EPS);
        float hh[2];
#pragma unroll
        for (int t = 0; t < 2; t++) {
            int j = lane + t * 32;
            float vv = (h1[t] - mean) * inv * gg[j] + gb[j];
            hh[t] = fmaxf(vv, 0.f);
        }
        float lg[3];
#pragma unroll
        for (int c = 0; c < 3; c++) {
            float acc = hh[0] * W2[c * 64 + lane] + hh[1] * W2[c * 64 + lane + 32];
#pragma unroll
            for (int off = 16; off; off >>= 1) acc += __shfl_xor_sync(0xffffffffu, acc, off);
            lg[c] = acc + b2[c];
        }
        if (lane == 0) {
            float m = fmaxf(lg[0], fmaxf(lg[1], lg[2]));
            float e0 = expf(lg[0] - m), e1 = expf(lg[1] - m), e2 = expf(lg[2] - m);
            float inv_s = 1.f / (e0 + e1 + e2);
            g_w3[h * 3 + 0] = e0 * inv_s;
            g_w3[h * 3 + 1] = e1 * inv_s;
            g_w3[h * 3 + 2] = e2 * inv_s;
        }
        return;
    }

#define ASM(b, r) (&pool[((b) * 16 + (r)) * 136])
#define BSM(b, r) (&pool[6528 + ((b) * 16 + (r)) * 72])
    const int h = hb >> 2, b = hb & 3;
    const int base = hb * Nn_;
    const int g = lane >> 2, q4 = lane & 3;
    const int m0 = ks * (Nn_ / KSPLIT);

    const float* fk = g_f + (size_t)ROWS * DIM;
    const float* fv = g_f + 2 * (size_t)ROWS * DIM;

    float acc[9][4];
#pragma unroll
    for (int j = 0; j < 9; j++)
#pragma unroll
        for (int c = 0; c < 4; c++) acc[j][c] = 0.f;

    const int srow = tid >> 4;
    const int dc = (tid & 15) * 4;
    const int auxr = tid >> 3, auxs = tid & 7;

    auto store_chunk = [&](int sb, float4 vv, float4 kk, float ki, float xv) {
        float* ar = ASM(sb, srow) + 2 * dc;
        ar[0] = vv.x; ar[1] = t32f(ki*vv.x);
        ar[2] = vv.y; ar[3] = t32f(ki*vv.y);
        ar[4] = vv.z; ar[5] = t32f(ki*vv.z);
        ar[6] = vv.w; ar[7] = t32f(ki*vv.w);
        *(float4*)(BSM(sb, srow) + dc) = kk;
        if (tid < 128) BSM(sb, auxr)[64 + auxs] = xv;
    };
    auto load_chunk = [&](int k0, float4& vv, float4& kk, float& ki, float& xv) {
        int m = m0 + k0 + srow;
        vv = *(const float4*)(fv + (size_t)(b*Nn_ + m)*DIM + h*DH + dc);
        kk = *(const float4*)(fk + (size_t)(b*Nn_ + m)*DIM + h*DH + dc);
        ki = g_kinv[base + m];
        xv = 0.f;
        if (tid < 128) {
            int mm = m0 + k0 + auxr;
            if (auxs == 0) xv = t32f(g_kvar [base + mm]);
            else if (auxs == 1) xv = t32f(g_kmean[base + mm]);
        }
    };

    const int L = (Nn_ / KSPLIT) / 16;

    {
        float4 vv, kk; float ki, xv;
        load_chunk(0, vv, kk, ki, xv);
        store_chunk(0, vv, kk, ki, xv);
    }
    float4 vvC, kkC; float kiC = 0.f, xvC = 0.f;
    load_chunk(16, vvC, kkC, kiC, xvC);
    __syncthreads();

    for (int j = 0; j < L; j++) {
        float4 vvN, kkN; float kiN = 0.f, xvN = 0.f;
        if (j + 2 < L) load_chunk((j + 2) * 16, vvN, kkN, kiN, xvN);
        const int cb = j % 3;
#pragma unroll
        for (int ks8 = 0; ks8 < 16; ks8 += 8) {
            unsigned af[4];
            const int mr = warp * 16 + g;
            af[0] = __float_as_uint(ASM(cb, ks8 + q4)[mr]);
            af[1] = __float_as_uint(ASM(cb, ks8 + q4)[mr + 8]);
            af[2] = __float_as_uint(ASM(cb, ks8 + 4 + q4)[mr]);
            af[3] = __float_as_uint(ASM(cb, ks8 + 4 + q4)[mr + 8]);
#pragma unroll
            for (int nt = 0; nt < 9; nt++) {
                unsigned bf[2];
                bf[0] = __float_as_uint(BSM(cb, ks8 + q4)[nt * 8 + g]);
                bf[1] = __float_as_uint(BSM(cb, ks8 + 4 + q4)[nt * 8 + g]);
                mma8(acc[nt], af, bf);
            }
        }
        if (j + 1 < L) store_chunk((j + 1) % 3, vvC, kkC, kiC, xvC);
        __syncthreads();
        vvC = vvN; kkC = kkN; kiC = kiN; xvC = xvN;
    }

    const int row0 = warp * 16 + g;
#pragma unroll
    for (int nt = 0; nt < 9; nt++) {
        const int col = nt * 8 + 2 * q4;
        atomicAdd(&g_Mr[hb][row0][col],         acc[nt][0]);
        atomicAdd(&g_Mr[hb][row0][col + 1],     acc[nt][1]);
        atomicAdd(&g_Mr[hb][row0 + 8][col],     acc[nt][2]);
        atomicAdd(&g_Mr[hb][row0 + 8][col + 1], acc[nt][3]);
    }
#undef ASM
#undef BSM
}

// ================ pgemm: single smem fill (K=64), one barrier ================
__global__ void __launch_bounds__(256) pgemm_kernel()
{
    extern __shared__ float psm[];
    float* As = psm;                 // [64][136]
    float* Bs = psm + 64 * 136;      // [64][136]
    const int tid = threadIdx.x;
    const int lane = tid & 31, warp = tid >> 5;
    const int wm = (warp >> 2) * 64, wn = (warp & 3) * 32;
    const int hb = blockIdx.y, h = hb >> 2, b = hb & 3;
    const int q0 = blockIdx.x * 128;
    const int base = hb * Nn_;
    const int g = lane >> 2, q4 = lane & 3;

    const float* fq = g_f;

    float acc[4][4][4];
#pragma unroll
    for (int i = 0; i < 4; i++)
#pragma unroll
        for (int j = 0; j < 4; j++)
#pragma unroll
            for (int c = 0; c < 4; c++) acc[i][j][c] = 0.f;

    const int srow = tid >> 1, skc = (tid & 1) * 8;
    const float* Apt = fq + (size_t)(b * Nn_ + q0 + srow) * DIM + h * DH + skc;
    const float* Wpt = &g_Mr[hb][srow][skc];

#pragma unroll
    for (int k0 = 0; k0 < DH; k0 += 16) {
        float4 a0 = *(const float4*)(Apt + k0);
        float4 a1 = *(const float4*)(Apt + k0 + 4);
        float4 w0 = *(const float4*)(Wpt + k0);
        float4 w1 = *(const float4*)(Wpt + k0 + 4);
        float* ac = &As[(k0 + skc) * 136 + srow];
        ac[0*136] = a0.x; ac[1*136] = a0.y; ac[2*136] = a0.z; ac[3*136] = a0.w;
        ac[4*136] = a1.x; ac[5*136] = a1.y; ac[6*136] = a1.z; ac[7*136] = a1.w;
        float* bc = &Bs[(k0 + skc) * 136 + srow];
        bc[0*136] = t32f(w0.x); bc[1*136] = t32f(w0.y); bc[2*136] = t32f(w0.z); bc[3*136] = t32f(w0.w);
        bc[4*136] = t32f(w1.x); bc[5*136] = t32f(w1.y); bc[6*136] = t32f(w1.z); bc[7*136] = t32f(w1.w);
    }
    __syncthreads();

#pragma unroll
    for (int ks = 0; ks < DH; ks += 8) {
        unsigned af[4][4], bf[4][2];
#pragma unroll
        for (int mt = 0; mt < 4; mt++) {
            int mr = wm + mt * 16 + g;
            af[mt][0] = __float_as_uint(As[(ks + q4) * 136 + mr]);
            af[mt][1] = __float_as_uint(As[(ks + q4) * 136 + mr + 8]);
            af[mt][2] = __float_as_uint(As[(ks + 4 + q4) * 136 + mr]);
            af[mt][3] = __float_as_uint(As[(ks + 4 + q4) * 136 + mr + 8]);
        }
#pragma unroll
        for (int nt = 0; nt < 4; nt++) {
            int nc = wn + nt * 8 + g;
            bf[nt][0] = __float_as_uint(Bs[(ks + q4) * 136 + nc]);
            bf[nt][1] = __float_as_uint(Bs[(ks + 4 + q4) * 136 + nc]);
        }
#pragma unroll
        for (int mt = 0; mt < 4; mt++)
#pragma unroll
            for (int nt = 0; nt < 4; nt++)
                mma8(acc[mt][nt], af[mt], bf[nt]);
    }

    const float cw = g_w3[h * 3 + 0], covw = g_w3[h * 3 + 1], vw = g_w3[h * 3 + 2];
#pragma unroll
    for (int mt = 0; mt < 4; mt++) {
        const int row0 = q0 + wm + mt * 16 + g;
        const float qi0 = g_qinv[base + row0],     qm0 = g_qmean[base + row0],     qv0 = g_qvar[base + row0];
        const float qi1 = g_qinv[base + row0 + 8], qm1 = g_qmean[base + row0 + 8], qv1 = g_qvar[base + row0 + 8];
#pragma unroll
        for (int nt = 0; nt < 4; nt++) {
            const int col = wn + nt * 8 + 2 * q4;
            const int d = col >> 1;
            const float Skv = g_Mr[hb][col][64];
            const float Skm = g_Mr[hb][col][65];
            float o0 = cw * qi0 * acc[mt][nt][1] + (covw / DH) * acc[mt][nt][0]
                     + (vw / DH) * qv0 * Skv - covw * qm0 * Skm;
            float o1 = cw * qi1 * acc[mt][nt][3] + (covw / DH) * acc[mt][nt][2]
                     + (vw / DH) * qv1 * Skv - covw * qm1 * Skm;
            g_ao[(size_t)(b * Nn_ + row0) * DIM + h * DH + d]     = t32f(o0);
            g_ao[(size_t)(b * Nn_ + row0 + 8) * DIM + h * DH + d] = t32f(o1);
        }
    }
}

// ---------------- launch ----------------
extern "C" void kernel_launch(void* const* d_in, const int* in_sizes, int n_in,
                              void* d_out, int out_size)
{
    const float* q    = (const float*)d_in[0];
    const float* k    = (const float*)d_in[1];
    const float* v    = (const float*)d_in[2];
    const float* Win  = (const float*)d_in[3];
    const float* Wout = (const float*)d_in[4];
    const float* bout = (const float*)d_in[5];
    const float* g1   = (const float*)d_in[6];
    const float* b1n  = (const float*)d_in[7];
    const float* g2   = (const float*)d_in[8];
    const float* b2n  = (const float*)d_in[9];
    const float* Wup  = (const float*)d_in[10];
    const float* bup  = (const float*)d_in[11];
    const float* Wdn  = (const float*)d_in[12];
    const float* bdn  = (const float*)d_in[13];
    const float* wpW1 = (const float*)d_in[14];
    const float* wpb1 = (const float*)d_in[15];
    const float* wpg  = (const float*)d_in[16];
    const float* wpb  = (const float*)d_in[17];
    const float* wpW2 = (const float*)d_in[18];
    const float* wpb2 = (const float*)d_in[19];
    float* out = (float*)d_out;

    float* xn;  cudaGetSymbolAddress((void**)&xn,  g_xn);
    float* f;   cudaGetSymbolAddress((void**)&f,   g_f);
    float* ao;  cudaGetSymbolAddress((void**)&ao,  g_ao);
    float* q2;  cudaGetSymbolAddress((void**)&q2,  g_q2);
    float* xn2; cudaGetSymbolAddress((void**)&xn2, g_xn2);
    float* u;   cudaGetSymbolAddress((void**)&u,   g_u);
    float* wr;  cudaGetSymbolAddress((void**)&wr,  g_wr);

    const int smem4 = TS * (128 + 128) * 20 * 4;   // 102400 B (MT=4)
    const int smem2 = TS * (64 + 128) * 20 * 4;    // 76800 B (MT=2)
    const int psmem = 2 * 64 * 136 * 4;            // 69632 B (pgemm)
    cudaFuncSetAttribute(tmm3_kernel<4,4>, cudaFuncAttributeMaxDynamicSharedMemorySize, smem4);
    cudaFuncSetAttribute(tmm3_kernel<2,4>, cudaFuncAttributeMaxDynamicSharedMemorySize, smem4);
    cudaFuncSetAttribute(tmm3_kernel<3,2>, cudaFuncAttributeMaxDynamicSharedMemorySize, smem2);
    cudaFuncSetAttribute(pgemm_kernel,     cudaFuncAttributeMaxDynamicSharedMemorySize, psmem);

    // 1. fused LN of q,k,v (tf32 out; also zeroes g_hg/g_Mr + rounds weights)
    ln3_kernel<<<3 * ROWS / 8, 256>>>(q, k, v, g1, b1n, xn, Win, Wout, Wup, Wdn);

    // 2. fused projection + per-row stats + per-head column sums
    tmm3_kernel<4, 4><<<dim3(DIM / 128, 3 * ROWS / 128), 256, smem4>>>(
        xn, wr + WR_WIN, nullptr, nullptr, f, 3 * ROWS, DIM, DIM);

    // 3. attention: Mcat build (+ folded gating MLP block) -> pgemm
    mbuild_kernel<<<dim3(KSPLIT, HB + 1), 256>>>(wpW1, wpb1, wpg, wpb, wpW2, wpb2);
    pgemm_kernel<<<dim3(Nn_ / 128, HB), 256, psmem>>>();

    // 4. attn out proj + residual -> q2
    tmm3_kernel<3, 2><<<dim3(DIM / 128, ROWS / 64), 256, smem2>>>(
        ao, wr + WR_WOUT, bout, q, q2, ROWS, DIM, DIM);

    // 5. LN2 (tf32 out)
    ln_kernel<<<ROWS / 8, 256>>>(q2, g2, b2n, xn2);

    // 6. MLP up + gelu (tf32 out)
    tmm3_kernel<2, 4><<<dim3(MLPD / 128, ROWS / 128), 256, smem4>>>(
        xn2, wr + WR_WUP, bup, nullptr, u, ROWS, MLPD, DIM);

    // 7. MLP down + residual -> out
    tmm3_kernel<3, 2><<<dim3(DIM / 128, ROWS / 64), 256, smem2>>>(
        u, wr + WR_WDN, bdn, q2, out, ROWS, DIM, MLPD);
}